// round 8
// baseline (speedup 1.0000x reference)
#include <cuda_runtime.h>
#include <cuda_bf16.h>

#define NUM_CLASSES 10
#define THREADS 256
#define CTAS_PER_SM 6
#define BLOCKS (148 * CTAS_PER_SM)   // one full wave at 6 CTAs/SM

// Global scratch (allocation-free rule: __device__ globals).
// Zero at module load; last block re-zeros after finalize -> deterministic replays.
__device__ float        g_sum[NUM_CLASSES];
__device__ float        g_cnt[NUM_CLASSES];
__device__ unsigned int g_ticket;

// One element: scatter squared error into per-thread smem column, count in packed u64.
// targets are always integer 0..9 (even where mask==0), so invalid elements can
// safely add 0.0f to their class sum; counts only increment when valid.
__device__ __forceinline__ void accum_one(float* __restrict__ s_sum, int tid,
                                          unsigned long long& cnt,
                                          float o, float t, int m) {
    int   c     = __float2int_rz(t);
    bool  valid = (m == 1);
    float d     = o - t;
    float sq    = valid ? d * d : 0.0f;
    s_sum[c * THREADS + tid] += sq;                    // LDS.32+FADD+STS.32
    cnt += valid ? (1ull << (6 * c)) : 0ull;           // 6-bit field per class (max 56/thread)
}

__global__ __launch_bounds__(THREADS, CTAS_PER_SM)
void loss_fused_kernel(const float4* __restrict__ o4,
                       const float4* __restrict__ t4,
                       const int4*   __restrict__ m4,
                       int nvec, int n,
                       float* __restrict__ out) {
    __shared__ float s_sum[NUM_CLASSES * THREADS];   // 10 KB
    __shared__ float s_cnt[NUM_CLASSES * THREADS];   // 10 KB
    __shared__ bool  s_is_last;

    const int tid = threadIdx.x;

    #pragma unroll
    for (int c = 0; c < NUM_CLASSES; c++)
        s_sum[c * THREADS + tid] = 0.0f;
    __syncthreads();

    const int gtid   = blockIdx.x * THREADS + tid;
    const int stride = gridDim.x * THREADS;

    unsigned long long cnt = 0ull;

    // unroll x2: 6 LDG.128 batched up front for MLP
    int i = gtid;
    for (; i + stride < nvec; i += 2 * stride) {
        float4 ov0 = __ldcs(&o4[i]);
        float4 ov1 = __ldcs(&o4[i + stride]);
        float4 tv0 = __ldcs(&t4[i]);
        float4 tv1 = __ldcs(&t4[i + stride]);
        int4   mv0 = __ldcs(&m4[i]);
        int4   mv1 = __ldcs(&m4[i + stride]);
        accum_one(s_sum, tid, cnt, ov0.x, tv0.x, mv0.x);
        accum_one(s_sum, tid, cnt, ov0.y, tv0.y, mv0.y);
        accum_one(s_sum, tid, cnt, ov0.z, tv0.z, mv0.z);
        accum_one(s_sum, tid, cnt, ov0.w, tv0.w, mv0.w);
        accum_one(s_sum, tid, cnt, ov1.x, tv1.x, mv1.x);
        accum_one(s_sum, tid, cnt, ov1.y, tv1.y, mv1.y);
        accum_one(s_sum, tid, cnt, ov1.z, tv1.z, mv1.z);
        accum_one(s_sum, tid, cnt, ov1.w, tv1.w, mv1.w);
    }
    if (i < nvec) {
        float4 ov = __ldcs(&o4[i]);
        float4 tv = __ldcs(&t4[i]);
        int4   mv = __ldcs(&m4[i]);
        accum_one(s_sum, tid, cnt, ov.x, tv.x, mv.x);
        accum_one(s_sum, tid, cnt, ov.y, tv.y, mv.y);
        accum_one(s_sum, tid, cnt, ov.z, tv.z, mv.z);
        accum_one(s_sum, tid, cnt, ov.w, tv.w, mv.w);
    }

    // scalar tail (n % 4), if any
    {
        const float* o1 = (const float*)o4;
        const float* t1 = (const float*)t4;
        const int*   m1 = (const int*)m4;
        for (int j = nvec * 4 + gtid; j < n; j += stride)
            accum_one(s_sum, tid, cnt, o1[j], t1[j], m1[j]);
    }

    // unpack per-thread counts into smem
    #pragma unroll
    for (int c = 0; c < NUM_CLASSES; c++)
        s_cnt[c * THREADS + tid] = (float)((unsigned)(cnt >> (6 * c)) & 63u);
    __syncthreads();

    // block tree-reduction over the 256 thread columns
    for (int s = THREADS / 2; s > 0; s >>= 1) {
        if (tid < s) {
            #pragma unroll
            for (int c = 0; c < NUM_CLASSES; c++) {
                s_sum[c * THREADS + tid] += s_sum[c * THREADS + tid + s];
                s_cnt[c * THREADS + tid] += s_cnt[c * THREADS + tid + s];
            }
        }
        __syncthreads();
    }

    // per-block partial -> global accumulators
    if (tid < NUM_CLASSES) {
        atomicAdd(&g_sum[tid], s_sum[tid * THREADS]);
        atomicAdd(&g_cnt[tid], s_cnt[tid * THREADS]);
        __threadfence();
    }
    __syncthreads();

    if (tid == 0) {
        unsigned int t = atomicAdd(&g_ticket, 1u);
        s_is_last = (t == (unsigned int)gridDim.x - 1u);
    }
    __syncthreads();

    // last-arriving block finalizes and resets scratch for the next replay
    if (s_is_last && tid == 0) {
        __threadfence();
        float loss = 0.0f;
        #pragma unroll
        for (int c = 0; c < NUM_CLASSES; c++) {
            float s  = atomicAdd(&g_sum[c], 0.0f);
            float nn = atomicAdd(&g_cnt[c], 0.0f);
            float le = (nn > 0.0f) ? (s / fmaxf(nn, 1.0f)) : 0.0f;
            out[1 + c] = le;                  // loss_each
            out[1 + NUM_CLASSES + c] = nn;    // class_n
            loss = fmaf(0.1f, le, loss);      // WEIGHT = 0.1 each
            g_sum[c] = 0.0f;
            g_cnt[c] = 0.0f;
        }
        out[0] = loss;
        g_ticket = 0u;
    }
}

extern "C" void kernel_launch(void* const* d_in, const int* in_sizes, int n_in,
                              void* d_out, int out_size) {
    const float* outputs = (const float*)d_in[0];
    const float* targets = (const float*)d_in[1];
    const int*   mask    = (const int*)d_in[2];
    int n    = in_sizes[0];
    int nvec = n / 4;

    loss_fused_kernel<<<BLOCKS, THREADS>>>((const float4*)outputs,
                                           (const float4*)targets,
                                           (const int4*)mask, nvec, n,
                                           (float*)d_out);
}

// round 11
// speedup vs baseline: 1.0067x; 1.0067x over previous
#include <cuda_runtime.h>
#include <cuda_bf16.h>

#define NUM_CLASSES 10
#define THREADS 256
#define CTAS_PER_SM 4
#define BLOCKS (148 * CTAS_PER_SM)

// Global scratch (allocation-free rule: __device__ globals).
// Zero at module load; last block re-zeros after finalize -> deterministic replays.
__device__ float        g_sum[NUM_CLASSES];
__device__ float        g_cnt[NUM_CLASSES];
__device__ unsigned int g_ticket;

// Squared error scatter into a per-thread smem column; count into packed
// 12-bit fields across two u64 registers (classes 0-4 in cA, 5-9 in cB).
// targets are integer 0..9 everywhere, so invalid elements add 0.0f to their
// real class (harmless); counts only increment when valid.
__device__ __forceinline__ void accum_one(float* __restrict__ s_col,
                                          unsigned long long& cA,
                                          unsigned long long& cB,
                                          float o, float t, int m) {
    int   c     = __float2int_rz(t);
    bool  valid = (m == 1);
    float d     = o - t;
    float sq    = valid ? d * d : 0.0f;
    s_col[c * THREADS] += sq;
    bool lo = (c < 5);
    int  f  = lo ? c : (c - 5);
    unsigned long long inc = valid ? (1ull << (12 * f)) : 0ull;
    if (lo) cA += inc; else cB += inc;
}

struct Grp {            // one pipelined group: 2 float4-triples = 8 elements
    float4 o0, o1, t0, t1;
    int4   m0, m1;
};

__device__ __forceinline__ Grp load_grp(const float4* __restrict__ o4,
                                        const float4* __restrict__ t4,
                                        const int4*   __restrict__ m4,
                                        int i, int stride) {
    Grp g;
    g.o0 = __ldcs(&o4[i]);
    g.o1 = __ldcs(&o4[i + stride]);
    g.t0 = __ldcs(&t4[i]);
    g.t1 = __ldcs(&t4[i + stride]);
    g.m0 = __ldcs(&m4[i]);
    g.m1 = __ldcs(&m4[i + stride]);
    return g;
}

__device__ __forceinline__ void process_grp(const Grp& g,
                                            float* __restrict__ sA,
                                            float* __restrict__ sB,
                                            unsigned long long& cA,
                                            unsigned long long& cB) {
    // even elements -> sA chain, odd elements -> sB chain (independent)
    accum_one(sA, cA, cB, g.o0.x, g.t0.x, g.m0.x);
    accum_one(sB, cA, cB, g.o0.y, g.t0.y, g.m0.y);
    accum_one(sA, cA, cB, g.o0.z, g.t0.z, g.m0.z);
    accum_one(sB, cA, cB, g.o0.w, g.t0.w, g.m0.w);
    accum_one(sA, cA, cB, g.o1.x, g.t1.x, g.m1.x);
    accum_one(sB, cA, cB, g.o1.y, g.t1.y, g.m1.y);
    accum_one(sA, cA, cB, g.o1.z, g.t1.z, g.m1.z);
    accum_one(sB, cA, cB, g.o1.w, g.t1.w, g.m1.w);
}

__global__ __launch_bounds__(THREADS, CTAS_PER_SM)
void loss_fused_kernel(const float4* __restrict__ o4,
                       const float4* __restrict__ t4,
                       const int4*   __restrict__ m4,
                       int nvec, int n,
                       float* __restrict__ out) {
    __shared__ float s_sumA[NUM_CLASSES * THREADS];   // 10 KB
    __shared__ float s_sumB[NUM_CLASSES * THREADS];   // 10 KB
    __shared__ float s_cnt [NUM_CLASSES * THREADS];   // 10 KB
    __shared__ bool  s_is_last;

    const int tid = threadIdx.x;

    #pragma unroll
    for (int c = 0; c < NUM_CLASSES; c++) {
        s_sumA[c * THREADS + tid] = 0.0f;
        s_sumB[c * THREADS + tid] = 0.0f;
    }
    __syncthreads();

    float* sA = &s_sumA[tid];
    float* sB = &s_sumB[tid];

    const int gtid   = blockIdx.x * THREADS + tid;
    const int stride = gridDim.x * THREADS;

    unsigned long long cA = 0ull, cB = 0ull;

    // software-pipelined main loop: next group's 6 LDG.128 in flight while
    // processing the current group, so DRAM never idles during the RMW chain
    int i = gtid;
    if (i + stride < nvec) {
        Grp cur = load_grp(o4, t4, m4, i, stride);
        int inext = i + 2 * stride;
        while (inext + stride < nvec) {
            Grp nxt = load_grp(o4, t4, m4, inext, stride);
            process_grp(cur, sA, sB, cA, cB);
            cur = nxt;
            inext += 2 * stride;
        }
        process_grp(cur, sA, sB, cA, cB);
        i = inext;
    }
    // leftover single float4 groups
    for (; i < nvec; i += stride) {
        float4 ov = __ldcs(&o4[i]);
        float4 tv = __ldcs(&t4[i]);
        int4   mv = __ldcs(&m4[i]);
        accum_one(sA, cA, cB, ov.x, tv.x, mv.x);
        accum_one(sB, cA, cB, ov.y, tv.y, mv.y);
        accum_one(sA, cA, cB, ov.z, tv.z, mv.z);
        accum_one(sB, cA, cB, ov.w, tv.w, mv.w);
    }
    // scalar tail (n % 4), if any
    {
        const float* o1 = (const float*)o4;
        const float* t1 = (const float*)t4;
        const int*   m1 = (const int*)m4;
        for (int j = nvec * 4 + gtid; j < n; j += stride)
            accum_one(sA, cA, cB, o1[j], t1[j], m1[j]);
    }

    // fold B into A, unpack counts
    #pragma unroll
    for (int c = 0; c < NUM_CLASSES; c++) {
        s_sumA[c * THREADS + tid] += s_sumB[c * THREADS + tid];
        unsigned long long w = (c < 5) ? cA : cB;
        s_cnt[c * THREADS + tid] =
            (float)((unsigned)(w >> (12 * (c < 5 ? c : c - 5))) & 0xFFFu);
    }
    __syncthreads();

    // block tree-reduction over the 256 thread columns
    for (int s = THREADS / 2; s > 0; s >>= 1) {
        if (tid < s) {
            #pragma unroll
            for (int c = 0; c < NUM_CLASSES; c++) {
                s_sumA[c * THREADS + tid] += s_sumA[c * THREADS + tid + s];
                s_cnt [c * THREADS + tid] += s_cnt [c * THREADS + tid + s];
            }
        }
        __syncthreads();
    }

    // per-block partial -> global accumulators
    if (tid < NUM_CLASSES) {
        atomicAdd(&g_sum[tid], s_sumA[tid * THREADS]);
        atomicAdd(&g_cnt[tid], s_cnt[tid * THREADS]);
        __threadfence();
    }
    __syncthreads();

    if (tid == 0) {
        unsigned int t = atomicAdd(&g_ticket, 1u);
        s_is_last = (t == (unsigned int)gridDim.x - 1u);
    }
    __syncthreads();

    // last-arriving block finalizes and resets scratch for the next replay
    if (s_is_last && tid == 0) {
        __threadfence();
        float loss = 0.0f;
        #pragma unroll
        for (int c = 0; c < NUM_CLASSES; c++) {
            float s  = atomicAdd(&g_sum[c], 0.0f);
            float nn = atomicAdd(&g_cnt[c], 0.0f);
            float le = (nn > 0.0f) ? (s / fmaxf(nn, 1.0f)) : 0.0f;
            out[1 + c] = le;                  // loss_each
            out[1 + NUM_CLASSES + c] = nn;    // class_n
            loss = fmaf(0.1f, le, loss);      // WEIGHT = 0.1 each
            g_sum[c] = 0.0f;
            g_cnt[c] = 0.0f;
        }
        out[0] = loss;
        g_ticket = 0u;
    }
}

extern "C" void kernel_launch(void* const* d_in, const int* in_sizes, int n_in,
                              void* d_out, int out_size) {
    const float* outputs = (const float*)d_in[0];
    const float* targets = (const float*)d_in[1];
    const int*   mask    = (const int*)d_in[2];
    int n    = in_sizes[0];
    int nvec = n / 4;

    loss_fused_kernel<<<BLOCKS, THREADS>>>((const float4*)outputs,
                                           (const float4*)targets,
                                           (const int4*)mask, nvec, n,
                                           (float*)d_out);
}